// round 4
// baseline (speedup 1.0000x reference)
#include <cuda_runtime.h>
#include <cuda_fp16.h>
#include <cstdint>

// ============================================================================
// y[M,N] = x[M,K] @ (qw*sw)^T + bias   M=8192, N=4096, K=4096
// x fp32, qw int32 (int8 values), sw fp32 scalar, bias fp32[N], out fp32.
//
// Build target is compute_103 (NOT 103a) => no tcgen05. Use arch-generic
// mma.sync.m16n8k16 fp16 (fp32 accum). Weights are EXACT in fp16 (|q|<=128,
// 11-bit mantissa); x rounded to fp16 gives L2 rel_err ~ 2.8e-4 < 1e-3.
// ============================================================================

#define MDIM 8192
#define NDIM 4096
#define KDIM 4096

#define BM 128
#define BN 256
#define BK 64
#define STAGES 3
#define KITERS (KDIM / BK)          // 64

#define ROW_HALFS (BK + 8)           // 72 halfs = 144 B (conflict-free ldmatrix)
#define ROW_BYTES (ROW_HALFS * 2)
#define A_STAGE_BYTES (BM * ROW_BYTES)             // 18432
#define B_STAGE_BYTES (BN * ROW_BYTES)             // 36864
#define STAGE_BYTES (A_STAGE_BYTES + B_STAGE_BYTES)
#define SMEM_TOTAL (STAGES * STAGE_BYTES)          // 165888 B

// ---------------- scratch (static device globals: allocation-free) ----------
__device__ __half g_xh[(size_t)MDIM * KDIM];  // 64 MB
__device__ __half g_w[(size_t)NDIM * KDIM];   // 32 MB

// ---------------- conversion kernels ----------------------------------------
__global__ __launch_bounds__(256) void convert_w_kernel(const int* __restrict__ qw) {
    size_t idx = (size_t)blockIdx.x * blockDim.x + threadIdx.x;  // one int4 (4 weights)
    const int4 v = reinterpret_cast<const int4*>(qw)[idx];
    __half2* w2 = reinterpret_cast<__half2*>(g_w);
    w2[2 * idx + 0] = __floats2half2_rn((float)v.x, (float)v.y);
    w2[2 * idx + 1] = __floats2half2_rn((float)v.z, (float)v.w);
}

__global__ __launch_bounds__(256) void convert_x_kernel(const float* __restrict__ x) {
    size_t idx = (size_t)blockIdx.x * blockDim.x + threadIdx.x;  // one float4
    const float4 v = reinterpret_cast<const float4*>(x)[idx];
    __half2* xh2 = reinterpret_cast<__half2*>(g_xh);
    xh2[2 * idx + 0] = __floats2half2_rn(v.x, v.y);
    xh2[2 * idx + 1] = __floats2half2_rn(v.z, v.w);
}

// ---------------- GEMM kernel ------------------------------------------------
__global__ __launch_bounds__(256, 1) void gemm_kernel(
    float* __restrict__ out,
    const float* __restrict__ swp,
    const float* __restrict__ bias) {
    extern __shared__ char smem[];

    const int tid = threadIdx.x;
    const int lane = tid & 31;
    const int wid = tid >> 5;
    const int wm = (wid & 1) * 64;   // warp m offset within CTA (2 warps in m)
    const int wn = (wid >> 1) * 64;  // warp n offset within CTA (4 warps in n)
    const int m0 = blockIdx.y * BM;
    const int n0 = blockIdx.x * BN;

    const uint32_t sbase = (uint32_t)__cvta_generic_to_shared(smem);

    const __half* gA = g_xh + (size_t)m0 * KDIM;
    const __half* gW = g_w + (size_t)n0 * KDIM;

    float acc[4][8][4];
#pragma unroll
    for (int mi = 0; mi < 4; ++mi)
#pragma unroll
        for (int n = 0; n < 8; ++n)
#pragma unroll
            for (int j = 0; j < 4; ++j) acc[mi][n][j] = 0.f;

    // ---- producer: load tile `it` into stage `s` (all 256 threads) ----------
    auto load_tile = [&](int it, int s) {
        const int k0 = it * BK;
        const uint32_t As = sbase + s * STAGE_BYTES;
        const uint32_t Bs = As + A_STAGE_BYTES;
        // A: 128 rows x 8 chunks of 16B -> 1024 chunks, 4 per thread
#pragma unroll
        for (int i = 0; i < 4; ++i) {
            const int c = tid + i * 256;
            const int r = c >> 3, cc = c & 7;
            const uint32_t d = As + r * ROW_BYTES + cc * 16;
            const size_t gsrc = __cvta_generic_to_global(gA + (size_t)r * KDIM + k0 + cc * 8);
            asm volatile("cp.async.cg.shared.global [%0], [%1], 16;"
                         :: "r"(d), "l"(gsrc) : "memory");
        }
        // B: 256 rows x 8 chunks -> 2048 chunks, 8 per thread
#pragma unroll
        for (int i = 0; i < 8; ++i) {
            const int c = tid + i * 256;
            const int r = c >> 3, cc = c & 7;
            const uint32_t d = Bs + r * ROW_BYTES + cc * 16;
            const size_t gsrc = __cvta_generic_to_global(gW + (size_t)r * KDIM + k0 + cc * 8);
            asm volatile("cp.async.cg.shared.global [%0], [%1], 16;"
                         :: "r"(d), "l"(gsrc) : "memory");
        }
    };

    // ---- prologue: fill STAGES-1 stages -------------------------------------
    load_tile(0, 0);
    asm volatile("cp.async.commit_group;" ::: "memory");
    load_tile(1, 1);
    asm volatile("cp.async.commit_group;" ::: "memory");

    // ---- mainloop -----------------------------------------------------------
    for (int it = 0; it < KITERS; ++it) {
        asm volatile("cp.async.wait_group 1;" ::: "memory");
        __syncthreads();

        const int nt = it + (STAGES - 1);
        if (nt < KITERS) load_tile(nt, nt % STAGES);
        asm volatile("cp.async.commit_group;" ::: "memory");

        const int s = it % STAGES;
        const uint32_t As = sbase + s * STAGE_BYTES;
        const uint32_t Bs = As + A_STAGE_BYTES;

#pragma unroll
        for (int ks = 0; ks < BK / 16; ++ks) {
            const int k = ks * 16;
            uint32_t a[4][4], b[4][4];
#pragma unroll
            for (int mi = 0; mi < 4; ++mi) {
                const uint32_t ad = As + (wm + mi * 16 + (lane & 15)) * ROW_BYTES
                                       + (k + (lane >> 4) * 8) * 2;
                asm volatile("ldmatrix.sync.aligned.m8n8.x4.shared.b16 {%0,%1,%2,%3}, [%4];"
                             : "=r"(a[mi][0]), "=r"(a[mi][1]), "=r"(a[mi][2]), "=r"(a[mi][3])
                             : "r"(ad));
            }
#pragma unroll
            for (int nj = 0; nj < 4; ++nj) {
                const uint32_t bd = Bs + (wn + nj * 16 + ((lane >> 4) & 1) * 8 + (lane & 7)) * ROW_BYTES
                                       + (k + ((lane >> 3) & 1) * 8) * 2;
                asm volatile("ldmatrix.sync.aligned.m8n8.x4.shared.b16 {%0,%1,%2,%3}, [%4];"
                             : "=r"(b[nj][0]), "=r"(b[nj][1]), "=r"(b[nj][2]), "=r"(b[nj][3])
                             : "r"(bd));
            }
#pragma unroll
            for (int mi = 0; mi < 4; ++mi) {
#pragma unroll
                for (int n = 0; n < 8; ++n) {
                    float* c = acc[mi][n];
                    const uint32_t b0 = b[n >> 1][(n & 1) * 2];
                    const uint32_t b1 = b[n >> 1][(n & 1) * 2 + 1];
                    asm volatile(
                        "mma.sync.aligned.m16n8k16.row.col.f32.f16.f16.f32 "
                        "{%0,%1,%2,%3}, {%4,%5,%6,%7}, {%8,%9}, {%0,%1,%2,%3};"
                        : "+f"(c[0]), "+f"(c[1]), "+f"(c[2]), "+f"(c[3])
                        : "r"(a[mi][0]), "r"(a[mi][1]), "r"(a[mi][2]), "r"(a[mi][3]),
                          "r"(b0), "r"(b1));
                }
            }
        }
        __syncthreads();
    }

    // ---- epilogue: out = acc*sw + bias --------------------------------------
    const float swv = *swp;
#pragma unroll
    for (int mi = 0; mi < 4; ++mi) {
        const int mr = m0 + wm + mi * 16 + (lane >> 2);
        float* r0 = out + (size_t)mr * NDIM;
        float* r1 = out + (size_t)(mr + 8) * NDIM;
#pragma unroll
        for (int n = 0; n < 8; ++n) {
            const int nc = n0 + wn + n * 8 + (lane & 3) * 2;
            const float2 bv = *reinterpret_cast<const float2*>(bias + nc);
            float2 v0, v1;
            v0.x = acc[mi][n][0] * swv + bv.x;
            v0.y = acc[mi][n][1] * swv + bv.y;
            v1.x = acc[mi][n][2] * swv + bv.x;
            v1.y = acc[mi][n][3] * swv + bv.y;
            *reinterpret_cast<float2*>(r0 + nc) = v0;
            *reinterpret_cast<float2*>(r1 + nc) = v1;
        }
    }
}

// ---------------- launch -----------------------------------------------------
extern "C" void kernel_launch(void* const* d_in, const int* in_sizes, int n_in,
                              void* d_out, int out_size) {
    const float* x = (const float*)d_in[0];
    const int* qw = (const int*)d_in[1];
    const float* sw = (const float*)d_in[2];
    const float* bias = (const float*)d_in[3];
    float* out = (float*)d_out;
    (void)in_sizes; (void)n_in; (void)out_size;

    cudaFuncSetAttribute(gemm_kernel, cudaFuncAttributeMaxDynamicSharedMemorySize, SMEM_TOTAL);

    // qw: N*K = 16,777,216 ints -> 4,194,304 int4 loads
    convert_w_kernel<<<(NDIM * (size_t)KDIM) / 4 / 256, 256>>>(qw);
    // x: M*K = 33,554,432 floats -> 8,388,608 float4 loads
    convert_x_kernel<<<((size_t)MDIM * KDIM) / 4 / 256, 256>>>(x);

    dim3 grid(NDIM / BN, MDIM / BM);  // (16, 64)
    gemm_kernel<<<grid, 256, SMEM_TOTAL>>>(out, sw, bias);
}

// round 5
// speedup vs baseline: 1.0265x; 1.0265x over previous
#include <cuda_runtime.h>
#include <cuda_fp16.h>
#include <cstdint>

// ============================================================================
// y[M,N] = x[M,K] @ (qw*sw)^T + bias   M=8192, N=4096, K=4096
// x fp32, qw int32 (int8 values), sw fp32 scalar, bias fp32[N], out fp32.
//
// compute_103 target (no tcgen05) => mma.sync.m16n8k16 fp16 / fp32 accum.
// Weights EXACT in fp16 (|q|<=128); x->fp16 gives rel_err ~2e-4 < 1e-3.
//
// R4 changes vs R3 (838us):
//  - 4-stage cp.async ring (was 3), wait_group 2 => 2 groups in flight
//  - ONE __syncthreads per k-iter (was 2) — trailing sync proven redundant
//  - register fragment double-buffering: LDSM for kstep+1 overlaps HMMAs of kstep
// ============================================================================

#define MDIM 8192
#define NDIM 4096
#define KDIM 4096

#define BM 128
#define BN 256
#define BK 64
#define STAGES 4
#define KITERS (KDIM / BK)          // 64

#define ROW_HALFS (BK + 8)           // 72 halfs = 144 B (conflict-free ldmatrix)
#define ROW_BYTES (ROW_HALFS * 2)
#define A_STAGE_BYTES (BM * ROW_BYTES)             // 18432
#define B_STAGE_BYTES (BN * ROW_BYTES)             // 36864
#define STAGE_BYTES (A_STAGE_BYTES + B_STAGE_BYTES)  // 55296
#define SMEM_TOTAL (STAGES * STAGE_BYTES)            // 221184 B

// ---------------- scratch (static device globals: allocation-free) ----------
__device__ __half g_xh[(size_t)MDIM * KDIM];  // 64 MB
__device__ __half g_w[(size_t)NDIM * KDIM];   // 32 MB

// ---------------- conversion kernels ----------------------------------------
__global__ __launch_bounds__(256) void convert_w_kernel(const int* __restrict__ qw) {
    size_t idx = (size_t)blockIdx.x * blockDim.x + threadIdx.x;  // one int4 (4 weights)
    const int4 v = reinterpret_cast<const int4*>(qw)[idx];
    __half2* w2 = reinterpret_cast<__half2*>(g_w);
    w2[2 * idx + 0] = __floats2half2_rn((float)v.x, (float)v.y);
    w2[2 * idx + 1] = __floats2half2_rn((float)v.z, (float)v.w);
}

__global__ __launch_bounds__(256) void convert_x_kernel(const float* __restrict__ x) {
    size_t idx = (size_t)blockIdx.x * blockDim.x + threadIdx.x;  // one float4
    const float4 v = reinterpret_cast<const float4*>(x)[idx];
    __half2* xh2 = reinterpret_cast<__half2*>(g_xh);
    xh2[2 * idx + 0] = __floats2half2_rn(v.x, v.y);
    xh2[2 * idx + 1] = __floats2half2_rn(v.z, v.w);
}

// ---------------- GEMM kernel ------------------------------------------------
__global__ __launch_bounds__(256, 1) void gemm_kernel(
    float* __restrict__ out,
    const float* __restrict__ swp,
    const float* __restrict__ bias) {
    extern __shared__ char smem[];

    const int tid = threadIdx.x;
    const int lane = tid & 31;
    const int wid = tid >> 5;
    const int wm = (wid & 1) * 64;   // warp m offset within CTA (2 warps in m)
    const int wn = (wid >> 1) * 64;  // warp n offset within CTA (4 warps in n)
    const int m0 = blockIdx.y * BM;
    const int n0 = blockIdx.x * BN;

    const uint32_t sbase = (uint32_t)__cvta_generic_to_shared(smem);

    const __half* gA = g_xh + (size_t)m0 * KDIM;
    const __half* gW = g_w + (size_t)n0 * KDIM;

    float acc[4][8][4];
#pragma unroll
    for (int mi = 0; mi < 4; ++mi)
#pragma unroll
        for (int n = 0; n < 8; ++n)
#pragma unroll
            for (int j = 0; j < 4; ++j) acc[mi][n][j] = 0.f;

    // Per-thread LDSM base addresses (lane-dependent parts precomputed)
    const uint32_t a_row_off = (lane & 15) * ROW_BYTES + (lane >> 4) * 16;        // +k*2
    const uint32_t b_row_off = (((lane >> 4) & 1) * 8 + (lane & 7)) * ROW_BYTES
                               + (((lane >> 3) & 1) * 8) * 2;                      // +k*2

    // ---- producer: load tile `it` into stage `s` (all 256 threads) ----------
    auto load_tile = [&](int it, int s) {
        const int k0 = it * BK;
        const uint32_t As = sbase + s * STAGE_BYTES;
        const uint32_t Bs = As + A_STAGE_BYTES;
#pragma unroll
        for (int i = 0; i < 4; ++i) {           // A: 1024 16B chunks, 4/thread
            const int c = tid + i * 256;
            const int r = c >> 3, cc = c & 7;
            const uint32_t d = As + r * ROW_BYTES + cc * 16;
            const size_t gsrc = __cvta_generic_to_global(gA + (size_t)r * KDIM + k0 + cc * 8);
            asm volatile("cp.async.cg.shared.global [%0], [%1], 16;"
                         :: "r"(d), "l"(gsrc) : "memory");
        }
#pragma unroll
        for (int i = 0; i < 8; ++i) {           // B: 2048 chunks, 8/thread
            const int c = tid + i * 256;
            const int r = c >> 3, cc = c & 7;
            const uint32_t d = Bs + r * ROW_BYTES + cc * 16;
            const size_t gsrc = __cvta_generic_to_global(gW + (size_t)r * KDIM + k0 + cc * 8);
            asm volatile("cp.async.cg.shared.global [%0], [%1], 16;"
                         :: "r"(d), "l"(gsrc) : "memory");
        }
        asm volatile("cp.async.commit_group;" ::: "memory");
    };

    // fragment loader for one kstep (ks in 0..3) from stage base
    auto load_frags = [&](uint32_t As, uint32_t Bs, int ks, uint32_t a[4][4], uint32_t b[4][4]) {
        const uint32_t kb = ks * 32;  // k*2 bytes, k = ks*16
#pragma unroll
        for (int mi = 0; mi < 4; ++mi) {
            const uint32_t ad = As + (wm + mi * 16) * ROW_BYTES + a_row_off + kb;
            asm volatile("ldmatrix.sync.aligned.m8n8.x4.shared.b16 {%0,%1,%2,%3}, [%4];"
                         : "=r"(a[mi][0]), "=r"(a[mi][1]), "=r"(a[mi][2]), "=r"(a[mi][3])
                         : "r"(ad));
        }
#pragma unroll
        for (int nj = 0; nj < 4; ++nj) {
            const uint32_t bd = Bs + (wn + nj * 16) * ROW_BYTES + b_row_off + kb;
            asm volatile("ldmatrix.sync.aligned.m8n8.x4.shared.b16 {%0,%1,%2,%3}, [%4];"
                         : "=r"(b[nj][0]), "=r"(b[nj][1]), "=r"(b[nj][2]), "=r"(b[nj][3])
                         : "r"(bd));
        }
    };

    auto do_mmas = [&](uint32_t a[4][4], uint32_t b[4][4]) {
#pragma unroll
        for (int mi = 0; mi < 4; ++mi) {
#pragma unroll
            for (int n = 0; n < 8; ++n) {
                float* c = acc[mi][n];
                const uint32_t b0 = b[n >> 1][(n & 1) * 2];
                const uint32_t b1 = b[n >> 1][(n & 1) * 2 + 1];
                asm volatile(
                    "mma.sync.aligned.m16n8k16.row.col.f32.f16.f16.f32 "
                    "{%0,%1,%2,%3}, {%4,%5,%6,%7}, {%8,%9}, {%0,%1,%2,%3};"
                    : "+f"(c[0]), "+f"(c[1]), "+f"(c[2]), "+f"(c[3])
                    : "r"(a[mi][0]), "r"(a[mi][1]), "r"(a[mi][2]), "r"(a[mi][3]),
                      "r"(b0), "r"(b1));
            }
        }
    };

    // ---- prologue: fill STAGES-1 stages -------------------------------------
    load_tile(0, 0);
    load_tile(1, 1);
    load_tile(2, 2);

    uint32_t afrag[2][4][4], bfrag[2][4][4];

    // ---- mainloop: ONE sync per iter, frag double-buffer --------------------
    for (int it = 0; it < KITERS; ++it) {
        // wait until the stage we consume (loaded 3 groups ago) has landed
        asm volatile("cp.async.wait_group %0;" :: "n"(STAGES - 2) : "memory");
        __syncthreads();
        // All warps finished reading stage (it-1)%STAGES before this sync
        // (program order), so overwriting stage (it+3)%STAGES is safe.
        const int nt = it + (STAGES - 1);
        if (nt < KITERS) load_tile(nt, nt & (STAGES - 1));
        else asm volatile("cp.async.commit_group;" ::: "memory");

        const uint32_t As = sbase + (it & (STAGES - 1)) * STAGE_BYTES;
        const uint32_t Bs = As + A_STAGE_BYTES;

        load_frags(As, Bs, 0, afrag[0], bfrag[0]);
#pragma unroll
        for (int ks = 0; ks < BK / 16; ++ks) {
            if (ks < BK / 16 - 1)
                load_frags(As, Bs, ks + 1, afrag[(ks + 1) & 1], bfrag[(ks + 1) & 1]);
            do_mmas(afrag[ks & 1], bfrag[ks & 1]);
        }
    }

    // ---- epilogue: out = acc*sw + bias --------------------------------------
    const float swv = *swp;
#pragma unroll
    for (int mi = 0; mi < 4; ++mi) {
        const int mr = m0 + wm + mi * 16 + (lane >> 2);
        float* r0 = out + (size_t)mr * NDIM;
        float* r1 = out + (size_t)(mr + 8) * NDIM;
#pragma unroll
        for (int n = 0; n < 8; ++n) {
            const int nc = n0 + wn + n * 8 + (lane & 3) * 2;
            const float2 bv = *reinterpret_cast<const float2*>(bias + nc);
            float2 v0, v1;
            v0.x = acc[mi][n][0] * swv + bv.x;
            v0.y = acc[mi][n][1] * swv + bv.y;
            v1.x = acc[mi][n][2] * swv + bv.x;
            v1.y = acc[mi][n][3] * swv + bv.y;
            *reinterpret_cast<float2*>(r0 + nc) = v0;
            *reinterpret_cast<float2*>(r1 + nc) = v1;
        }
    }
}

// ---------------- launch -----------------------------------------------------
extern "C" void kernel_launch(void* const* d_in, const int* in_sizes, int n_in,
                              void* d_out, int out_size) {
    const float* x = (const float*)d_in[0];
    const int* qw = (const int*)d_in[1];
    const float* sw = (const float*)d_in[2];
    const float* bias = (const float*)d_in[3];
    float* out = (float*)d_out;
    (void)in_sizes; (void)n_in; (void)out_size;

    cudaFuncSetAttribute(gemm_kernel, cudaFuncAttributeMaxDynamicSharedMemorySize, SMEM_TOTAL);

    convert_w_kernel<<<(NDIM * (size_t)KDIM) / 4 / 256, 256>>>(qw);
    convert_x_kernel<<<((size_t)MDIM * KDIM) / 4 / 256, 256>>>(x);

    dim3 grid(NDIM / BN, MDIM / BM);  // (16, 64)
    gemm_kernel<<<grid, 256, SMEM_TOTAL>>>(out, sw, bias);
}